// round 1
// baseline (speedup 1.0000x reference)
#include <cuda_runtime.h>
#include <math.h>

#define B_ 512
#define T_ 8
#define K_ 8192
#define H_ 768
#define F_ 512
#define N1 (T_*F_)   /* 4096 */
#define EPSF 1e-8f
#define RMS_EPS 1e-6f

// Scratch + accumulators (no allocation allowed in kernel_launch)
__device__ float g_x[(size_t)B_ * N1];          // 8 MB: x, then normalized in place
__device__ double g_loss;
__device__ unsigned long long g_count;

__global__ void init_kernel() {
    g_loss = 0.0;
    g_count = 0ull;
}

// ---------------- GEMM1: x = features @ W1 + b1 ----------------
// A: (512,768) row-major, W: (768,4096) row-major, out -> g_x (512,4096)
__global__ __launch_bounds__(256, 2)
void gemm1_kernel(const float* __restrict__ A, const float* __restrict__ W,
                  const float* __restrict__ bias) {
    __shared__ float As[16][128 + 4];   // [k][m]
    __shared__ float Bs[16][128 + 4];   // [k][n]
    const int tid = threadIdx.x;
    const int tx = tid & 15;            // col group
    const int ty = tid >> 4;            // row group
    const int rowBase = blockIdx.y * 128;
    const int colBase = blockIdx.x * 128;

    float acc[8][8] = {};

    for (int k0 = 0; k0 < H_; k0 += 16) {
        #pragma unroll
        for (int i = 0; i < 8; i++) {
            int r = ty + i * 16;        // 0..127
            As[tx][r] = A[(rowBase + r) * H_ + k0 + tx];
        }
        #pragma unroll
        for (int i = 0; i < 8; i++) {
            int lin = tid + i * 256;
            int r = lin >> 7, c = lin & 127;
            Bs[r][c] = W[(k0 + r) * N1 + colBase + c];
        }
        __syncthreads();
        #pragma unroll
        for (int kk = 0; kk < 16; kk++) {
            float a[8], b[8];
            #pragma unroll
            for (int i = 0; i < 8; i++) a[i] = As[kk][ty + 16 * i];
            #pragma unroll
            for (int j = 0; j < 8; j++) b[j] = Bs[kk][tx + 16 * j];
            #pragma unroll
            for (int i = 0; i < 8; i++)
                #pragma unroll
                for (int j = 0; j < 8; j++)
                    acc[i][j] = fmaf(a[i], b[j], acc[i][j]);
        }
        __syncthreads();
    }

    #pragma unroll
    for (int i = 0; i < 8; i++) {
        int r = rowBase + ty + 16 * i;
        #pragma unroll
        for (int j = 0; j < 8; j++) {
            int c = colBase + tx + 16 * j;
            g_x[(size_t)r * N1 + c] = acc[i][j] + bias[c];
        }
    }
}

// ---------------- RMS norm in place per (b,t) segment of F=512 ----------------
__global__ void rms_kernel(const float* __restrict__ norm_w) {
    const int seg = blockIdx.x;                 // 0..4095 == b*8+t
    float* xp = g_x + (size_t)seg * F_;
    const int tid = threadIdx.x;                // 128 threads

    float v[4];
    float ss = 0.f;
    #pragma unroll
    for (int i = 0; i < 4; i++) { v[i] = xp[tid + i * 128]; ss = fmaf(v[i], v[i], ss); }

    #pragma unroll
    for (int o = 16; o > 0; o >>= 1) ss += __shfl_xor_sync(0xffffffffu, ss, o);
    __shared__ float red[4];
    if ((tid & 31) == 0) red[tid >> 5] = ss;
    __syncthreads();
    float total = red[0] + red[1] + red[2] + red[3];
    float scale = rsqrtf(total * (1.0f / F_) + RMS_EPS);

    #pragma unroll
    for (int i = 0; i < 4; i++)
        xp[tid + i * 128] = v[i] * scale * norm_w[tid + i * 128];
}

// ---------------- GEMM2 + full loss epilogue ----------------
// A = g_x (4096,512) normalized, Bm = W2 (512,8192).
// Micro-tile rows = all 8 t's of one b -> softmax/cumsum/loss fully in registers.
__global__ __launch_bounds__(256, 2)
void gemm2_loss_kernel(const float* __restrict__ W2, const float* __restrict__ b2,
                       const unsigned char* __restrict__ is_event,
                       const unsigned char* __restrict__ is_censored,
                       const float* __restrict__ ctr) {
    __shared__ float As[16][128 + 4];   // [k][m]
    __shared__ float Bs[16][128 + 4];   // [k][n]
    const int tid = threadIdx.x;
    const int tx = tid & 15;            // k group (cols strided by 16)
    const int ty = tid >> 4;            // b within tile (rows = ty*8 .. ty*8+7)
    const int rowBase = blockIdx.y * 128;     // = b_base * 8
    const int colBase = blockIdx.x * 128;
    const int bglob = (rowBase >> 3) + ty;    // global b for this thread

    float acc[8][8] = {};               // [t][j]

    for (int k0 = 0; k0 < F_; k0 += 16) {
        #pragma unroll
        for (int i = 0; i < 8; i++) {
            int r = ty + i * 16;
            As[tx][r] = g_x[(size_t)(rowBase + r) * F_ + k0 + tx];
        }
        #pragma unroll
        for (int i = 0; i < 8; i++) {
            int lin = tid + i * 256;
            int r = lin >> 7, c = lin & 127;
            Bs[r][c] = W2[(size_t)(k0 + r) * K_ + colBase + c];
        }
        __syncthreads();
        #pragma unroll
        for (int kk = 0; kk < 16; kk++) {
            float a[8], b[8];
            #pragma unroll
            for (int t = 0; t < 8; t++) a[t] = As[kk][ty * 8 + t];
            #pragma unroll
            for (int j = 0; j < 8; j++) b[j] = Bs[kk][tx + 16 * j];
            #pragma unroll
            for (int t = 0; t < 8; t++)
                #pragma unroll
                for (int j = 0; j < 8; j++)
                    acc[t][j] = fmaf(a[t], b[j], acc[t][j]);
        }
        __syncthreads();
    }

    // ---- epilogue: softmax over t, cumsum, clipping, event-selected loss ----
    float lloss = 0.f;
    int lcnt = 0;

    #pragma unroll
    for (int j = 0; j < 8; j++) {
        const int k = colBase + tx + 16 * j;
        const float bb = b2[k];
        float lg[8];
        float mx = -1e30f;
        #pragma unroll
        for (int t = 0; t < 8; t++) { lg[t] = acc[t][j] + bb; mx = fmaxf(mx, lg[t]); }
        float e[8];
        float s = 0.f;
        #pragma unroll
        for (int t = 0; t < 8; t++) { e[t] = __expf(lg[t] - mx); s += e[t]; }
        const float inv = 1.0f / s;

        const bool cen = is_censored[(size_t)bglob * K_ + k] != 0;
        float cdf = 0.f;
        #pragma unroll
        for (int t = 0; t < 8; t++) {
            const float p = e[t] * inv;
            if (is_event[((size_t)bglob * T_ + t) * K_ + k]) {
                float integrated = (t == 0) ? 1.0f : (1.0f - cdf);
                float p_s = fminf(fmaxf(p, EPSF), 1.0f - EPSF);
                float i_s = fminf(fmaxf(integrated, EPSF), 1.0f - EPSF);
                float sel;
                if (cen) {
                    float r = ctr[((size_t)bglob * T_ + t) * K_ + k];
                    i_s = fminf(fmaxf(i_s - r * p_s, EPSF), 1.0f - EPSF);
                    sel = i_s;
                } else {
                    sel = p_s;
                }
                lloss += __logf(sel);
                lcnt++;
            }
            cdf += p;
        }
    }

    // ---- block reduce -> double atomic ----
    #pragma unroll
    for (int o = 16; o > 0; o >>= 1) {
        lloss += __shfl_xor_sync(0xffffffffu, lloss, o);
        lcnt  += __shfl_xor_sync(0xffffffffu, lcnt, o);
    }
    __shared__ float rl[8];
    __shared__ int rc[8];
    if ((tid & 31) == 0) { rl[tid >> 5] = lloss; rc[tid >> 5] = lcnt; }
    __syncthreads();
    if (tid == 0) {
        float tl = 0.f; int tc = 0;
        #pragma unroll
        for (int w = 0; w < 8; w++) { tl += rl[w]; tc += rc[w]; }
        atomicAdd(&g_loss, (double)tl);
        atomicAdd(&g_count, (unsigned long long)tc);
    }
}

__global__ void finalize_kernel(float* __restrict__ out) {
    const double H_t = 2.0794415416798357;  // log(8)
    out[0] = (float)(-g_loss / ((double)g_count * H_t));
}

extern "C" void kernel_launch(void* const* d_in, const int* in_sizes, int n_in,
                              void* d_out, int out_size) {
    const float* features = (const float*)d_in[0];
    const float* W1       = (const float*)d_in[1];
    const float* b1       = (const float*)d_in[2];
    const float* norm_w   = (const float*)d_in[3];
    const float* W2       = (const float*)d_in[4];
    const float* b2       = (const float*)d_in[5];
    const unsigned char* is_event    = (const unsigned char*)d_in[6];
    const unsigned char* is_censored = (const unsigned char*)d_in[7];
    const float* ctr      = (const float*)d_in[8];
    float* out = (float*)d_out;

    init_kernel<<<1, 1>>>();

    dim3 g1(N1 / 128, B_ / 128);            // (32, 4)
    gemm1_kernel<<<g1, 256>>>(features, W1, b1);

    rms_kernel<<<B_ * T_, 128>>>(norm_w);   // 4096 segments

    dim3 g2(K_ / 128, (B_ * T_) / 128);     // (64, 32)
    gemm2_loss_kernel<<<g2, 256>>>(W2, b2, is_event, is_censored, ctr);

    finalize_kernel<<<1, 1>>>(out);
}

// round 7
// speedup vs baseline: 1.2994x; 1.2994x over previous
#include <cuda_runtime.h>
#include <cstdint>
#include <math.h>

#define B_ 512
#define T_ 8
#define K_ 8192
#define H_ 768
#define F_ 512
#define N1 4096
#define EPSF 1e-8f
#define RMS_EPS 1e-6f

typedef unsigned long long ull;

// ---------------- device scratch ----------------
__device__ float g_x[(size_t)B_ * N1];     // x fp32; rms-normalized in place
__device__ double g_loss;
__device__ unsigned long long g_count;

// ---------------- f32x2 helpers (Blackwell packed fp32 FMA) ----------------
__device__ __forceinline__ ull pack_dup(float v) {
    ull d; uint32_t r = __float_as_uint(v);
    asm("mov.b64 %0, {%1, %2};" : "=l"(d) : "r"(r), "r"(r));
    return d;
}
__device__ __forceinline__ void fma2(ull& acc, ull a, ull b) {
    asm("fma.rn.f32x2 %0, %1, %2, %0;" : "+l"(acc) : "l"(a), "l"(b));
}
__device__ __forceinline__ float2 unpack2(ull v) {
    uint32_t lo, hi;
    asm("mov.b64 {%0, %1}, %2;" : "=r"(lo), "=r"(hi) : "l"(v));
    return make_float2(__uint_as_float(lo), __uint_as_float(hi));
}

__global__ void init_kernel() { g_loss = 0.0; g_count = 0ull; }

// ---------------- shared f32x2 mainloop ----------------
// CTA 128(M) x 128(N), BK=16, 256 threads (tx 0-15 cols, ty 0-15 rows).
// Thread micro-tile: rows m = ty*8 .. ty*8+7 (t-pairs packed in f32x2),
// cols n = tx*4+{0..3} and tx*4+64+{0..3}.
// acc[tp][j]: lo = row ty*8+2tp, hi = row ty*8+2tp+1, col j.
template <int KTOT>
__device__ __forceinline__ void mainloop_f32x2(
    const float* __restrict__ A, int lda,
    const float* __restrict__ Bm, int ldb,
    int rowBase, int colBase,
    float (*As)[132], float (*Bs)[132], ull acc[4][8])
{
    const int tid = threadIdx.x;
    const int tx = tid & 15, ty = tid >> 4;

    for (int k0 = 0; k0 < KTOT; k0 += 16) {
        // As[kk][m] = A[rowBase+m][k0+kk]  (transposed store)
        #pragma unroll
        for (int i = 0; i < 8; i++) {
            int r = ty + i * 16;
            As[tx][r] = A[(size_t)(rowBase + r) * lda + k0 + tx];
        }
        // Bs[kk][n] = B[k0+kk][colBase+n]
        #pragma unroll
        for (int i = 0; i < 8; i++) {
            int lin = tid + i * 256;
            int r = lin >> 7, c = lin & 127;
            Bs[r][c] = Bm[(size_t)(k0 + r) * ldb + colBase + c];
        }
        __syncthreads();
        #pragma unroll
        for (int kk = 0; kk < 16; kk++) {
            // a: 8 contiguous rows -> 2x LDS.128 as packed f32x2 pairs
            ulonglong2 a01 = *reinterpret_cast<const ulonglong2*>(&As[kk][ty * 8]);
            ulonglong2 a23 = *reinterpret_cast<const ulonglong2*>(&As[kk][ty * 8 + 4]);
            ull ap[4] = {a01.x, a01.y, a23.x, a23.y};
            // b: 2x LDS.128, duplicate each scalar across the pair
            float4 bv0 = *reinterpret_cast<const float4*>(&Bs[kk][tx * 4]);
            float4 bv1 = *reinterpret_cast<const float4*>(&Bs[kk][tx * 4 + 64]);
            ull bd[8] = {pack_dup(bv0.x), pack_dup(bv0.y), pack_dup(bv0.z), pack_dup(bv0.w),
                         pack_dup(bv1.x), pack_dup(bv1.y), pack_dup(bv1.z), pack_dup(bv1.w)};
            #pragma unroll
            for (int tp = 0; tp < 4; tp++)
                #pragma unroll
                for (int j = 0; j < 8; j++)
                    fma2(acc[tp][j], ap[tp], bd[j]);
        }
        __syncthreads();
    }
}

// ---------------- GEMM1: x = feat @ W1 + b1 ----------------
__global__ __launch_bounds__(256)
void gemm1_kernel(const float* __restrict__ A, const float* __restrict__ W,
                  const float* __restrict__ bias) {
    __shared__ float As[16][132];
    __shared__ float Bs[16][132];
    const int tx = threadIdx.x & 15, ty = threadIdx.x >> 4;
    const int rowBase = blockIdx.y * 128, colBase = blockIdx.x * 128;

    ull acc[4][8];
    #pragma unroll
    for (int tp = 0; tp < 4; tp++)
        #pragma unroll
        for (int j = 0; j < 8; j++) acc[tp][j] = 0ull;

    mainloop_f32x2<H_>(A, H_, W, N1, rowBase, colBase, As, Bs, acc);

    const int c0 = colBase + tx * 4;
    float4 bb0 = *reinterpret_cast<const float4*>(&bias[c0]);
    float4 bb1 = *reinterpret_cast<const float4*>(&bias[c0 + 64]);
    #pragma unroll
    for (int tp = 0; tp < 4; tp++) {
        float2 v[8];
        #pragma unroll
        for (int j = 0; j < 8; j++) v[j] = unpack2(acc[tp][j]);
        int m0 = rowBase + ty * 8 + tp * 2;
        // row m0 (lo halves)
        *reinterpret_cast<float4*>(&g_x[(size_t)m0 * N1 + c0]) =
            make_float4(v[0].x + bb0.x, v[1].x + bb0.y, v[2].x + bb0.z, v[3].x + bb0.w);
        *reinterpret_cast<float4*>(&g_x[(size_t)m0 * N1 + c0 + 64]) =
            make_float4(v[4].x + bb1.x, v[5].x + bb1.y, v[6].x + bb1.z, v[7].x + bb1.w);
        // row m0+1 (hi halves)
        *reinterpret_cast<float4*>(&g_x[(size_t)(m0 + 1) * N1 + c0]) =
            make_float4(v[0].y + bb0.x, v[1].y + bb0.y, v[2].y + bb0.z, v[3].y + bb0.w);
        *reinterpret_cast<float4*>(&g_x[(size_t)(m0 + 1) * N1 + c0 + 64]) =
            make_float4(v[4].y + bb1.x, v[5].y + bb1.y, v[6].y + bb1.z, v[7].y + bb1.w);
    }
}

// ---------------- RMS norm in place (R1 verbatim) ----------------
__global__ void rms_kernel(const float* __restrict__ norm_w) {
    const int seg = blockIdx.x;                 // b*8+t
    float* xp = g_x + (size_t)seg * F_;
    const int tid = threadIdx.x;                // 128

    float v[4];
    float ss = 0.f;
    #pragma unroll
    for (int i = 0; i < 4; i++) { v[i] = xp[tid + i * 128]; ss = fmaf(v[i], v[i], ss); }
    #pragma unroll
    for (int o = 16; o > 0; o >>= 1) ss += __shfl_xor_sync(0xffffffffu, ss, o);
    __shared__ float red[4];
    if ((tid & 31) == 0) red[tid >> 5] = ss;
    __syncthreads();
    float scale = rsqrtf((red[0] + red[1] + red[2] + red[3]) * (1.0f / F_) + RMS_EPS);
    #pragma unroll
    for (int i = 0; i < 4; i++)
        xp[tid + i * 128] = v[i] * scale * norm_w[tid + i * 128];
}

// ---------------- GEMM2 + loss epilogue (R1 math, f32x2 mainloop) ----------------
__global__ __launch_bounds__(256)
void gemm2_loss_kernel(const float* __restrict__ W2, const float* __restrict__ b2,
                       const unsigned char* __restrict__ is_event,
                       const unsigned char* __restrict__ is_cen,
                       const float* __restrict__ ctr) {
    __shared__ float As[16][132];
    __shared__ float Bs[16][132];
    const int tid = threadIdx.x;
    const int tx = tid & 15, ty = tid >> 4;
    const int rowBase = blockIdx.y * 128, colBase = blockIdx.x * 128;
    const int bglob = blockIdx.y * 16 + ty;     // thread owns all 8 t of this b

    ull acc[4][8];
    #pragma unroll
    for (int tp = 0; tp < 4; tp++)
        #pragma unroll
        for (int j = 0; j < 8; j++) acc[tp][j] = 0ull;

    mainloop_f32x2<F_>(g_x, F_, W2, K_, rowBase, colBase, As, Bs, acc);

    // ---- epilogue: per column j, softmax over t in registers (R1-proven math) ----
    float lloss = 0.f;
    int lcnt = 0;
    #pragma unroll
    for (int j = 0; j < 8; j++) {
        const int k = colBase + tx * 4 + (j & 3) + ((j >= 4) ? 64 : 0);
        const float bb = b2[k];
        float lg[8];
        #pragma unroll
        for (int tp = 0; tp < 4; tp++) {
            float2 p2 = unpack2(acc[tp][j]);
            lg[tp * 2]     = p2.x + bb;
            lg[tp * 2 + 1] = p2.y + bb;
        }
        float mx = lg[0];
        #pragma unroll
        for (int t = 1; t < 8; t++) mx = fmaxf(mx, lg[t]);
        float e[8], s = 0.f;
        #pragma unroll
        for (int t = 0; t < 8; t++) { e[t] = __expf(lg[t] - mx); s += e[t]; }
        const float inv = 1.0f / s;

        const bool cen = is_cen[(size_t)bglob * K_ + k] != 0;
        float cdf = 0.f;
        #pragma unroll
        for (int t = 0; t < 8; t++) {
            const float p = e[t] * inv;
            if (is_event[((size_t)bglob * T_ + t) * K_ + k]) {
                float integrated = (t == 0) ? 1.0f : (1.0f - cdf);
                float p_s = fminf(fmaxf(p, EPSF), 1.0f - EPSF);
                float i_s = fminf(fmaxf(integrated, EPSF), 1.0f - EPSF);
                float sel;
                if (cen) {
                    float r = ctr[((size_t)bglob * T_ + t) * K_ + k];
                    i_s = fminf(fmaxf(i_s - r * p_s, EPSF), 1.0f - EPSF);
                    sel = i_s;
                } else {
                    sel = p_s;
                }
                lloss += __logf(sel);
                lcnt++;
            }
            cdf += p;
        }
    }

    // block reduce -> double atomics (R1 verbatim)
    #pragma unroll
    for (int o = 16; o > 0; o >>= 1) {
        lloss += __shfl_xor_sync(0xffffffffu, lloss, o);
        lcnt  += __shfl_xor_sync(0xffffffffu, lcnt, o);
    }
    __shared__ float rl[8];
    __shared__ int rc[8];
    if ((tid & 31) == 0) { rl[tid >> 5] = lloss; rc[tid >> 5] = lcnt; }
    __syncthreads();
    if (tid == 0) {
        float tl = 0.f; int tc = 0;
        #pragma unroll
        for (int w = 0; w < 8; w++) { tl += rl[w]; tc += rc[w]; }
        atomicAdd(&g_loss, (double)tl);
        atomicAdd(&g_count, (unsigned long long)tc);
    }
}

__global__ void finalize_kernel(float* __restrict__ out) {
    const double H_t = 2.0794415416798357;      // log(8)
    out[0] = (float)(-g_loss / ((double)g_count * H_t));
}

// ---------------- launch ----------------
extern "C" void kernel_launch(void* const* d_in, const int* in_sizes, int n_in,
                              void* d_out, int out_size) {
    const float* features = (const float*)d_in[0];
    const float* W1       = (const float*)d_in[1];
    const float* b1       = (const float*)d_in[2];
    const float* norm_w   = (const float*)d_in[3];
    const float* W2       = (const float*)d_in[4];
    const float* b2       = (const float*)d_in[5];
    const unsigned char* is_event    = (const unsigned char*)d_in[6];
    const unsigned char* is_censored = (const unsigned char*)d_in[7];
    const float* ctr      = (const float*)d_in[8];
    float* out = (float*)d_out;

    init_kernel<<<1, 1>>>();

    gemm1_kernel<<<dim3(N1 / 128, B_ / 128), 256>>>(features, W1, b1);
    rms_kernel<<<B_ * T_, 128>>>(norm_w);

    gemm2_loss_kernel<<<dim3(K_ / 128, (B_ * T_) / 128), 256>>>(W2, b2, is_event,
                                                                is_censored, ctr);

    finalize_kernel<<<1, 1>>>(out);
}

// round 8
// speedup vs baseline: 1.3560x; 1.0435x over previous
#include <cuda_runtime.h>
#include <cstdint>
#include <math.h>

#define B_ 512
#define T_ 8
#define K_ 8192
#define H_ 768
#define F_ 512
#define N1 4096
#define EPSF 1e-8f
#define RMS_EPS 1e-6f

typedef unsigned long long ull;

// ---------------- device scratch ----------------
__device__ float g_x[(size_t)B_ * N1];     // x fp32; rms-normalized in place
__device__ double g_loss;
__device__ unsigned long long g_count;

// ---------------- helpers ----------------
__device__ __forceinline__ uint32_t smem_u32(const void* p) {
    uint32_t a;
    asm("{ .reg .u64 t; cvta.to.shared.u64 t, %1; cvt.u32.u64 %0, t; }" : "=r"(a) : "l"(p));
    return a;
}
#define CP_ASYNC16(smaddr, gptr) \
    asm volatile("cp.async.cg.shared.global [%0], [%1], 16;" :: "r"(smaddr), "l"(gptr))
#define CP_COMMIT() asm volatile("cp.async.commit_group;" ::: "memory")
#define CP_WAIT0()  asm volatile("cp.async.wait_group 0;" ::: "memory")

__device__ __forceinline__ ull pack_dup(float v) {
    ull d; uint32_t r = __float_as_uint(v);
    asm("mov.b64 %0, {%1, %2};" : "=l"(d) : "r"(r), "r"(r));
    return d;
}
__device__ __forceinline__ void fma2(ull& acc, ull a, ull b) {
    asm("fma.rn.f32x2 %0, %1, %2, %0;" : "+l"(acc) : "l"(a), "l"(b));
}
__device__ __forceinline__ float2 unpack2(ull v) {
    uint32_t lo, hi;
    asm("mov.b64 {%0, %1}, %2;" : "=r"(lo), "=r"(hi) : "l"(v));
    return make_float2(__uint_as_float(lo), __uint_as_float(hi));
}

__global__ void init_kernel() { g_loss = 0.0; g_count = 0ull; }

// ---------------- double-buffered f32x2 mainloop ----------------
// CTA 128(M) x 128(N), BK=16, 256 threads (tx = tid&15 cols, ty = tid>>4 rows).
// Thread micro-tile: rows ty*8..ty*8+7 (f32x2 pairs), cols tx*4+{0..3}, +64.
// SMEM layout (dynamic): As0, As1, Bs0, Bs1, each [16][132] fp32.
#define TSZ (16 * 132)
template <int KTOT>
__device__ __forceinline__ void mainloop_f32x2(
    const float* __restrict__ A, int lda,
    const float* __restrict__ Bm, int ldb,
    int rowBase, int colBase, float* sm, ull acc[4][8])
{
    const int tid = threadIdx.x;
    const int tx = tid & 15, ty = tid >> 4;
    float* As[2] = {sm, sm + TSZ};
    float* Bs[2] = {sm + 2 * TSZ, sm + 3 * TSZ};
    const uint32_t bsm[2] = {smem_u32(Bs[0]), smem_u32(Bs[1])};

    // A staging: thread loads 2 float4 (2 rows x 4 consecutive k)
    const int ar[2] = {(tid + 0) >> 2, (tid + 256) >> 2};       // rows 0..127
    const int aq[2] = {(tid + 0) & 3, (tid + 256) & 3};         // k-quad 0..3

    auto load_a = [&](int c, float4 areg[2]) {
        #pragma unroll
        for (int j = 0; j < 2; j++)
            areg[j] = *reinterpret_cast<const float4*>(
                A + (size_t)(rowBase + ar[j]) * lda + c * 16 + aq[j] * 4);
    };
    auto store_a = [&](int buf, const float4 areg[2]) {
        #pragma unroll
        for (int j = 0; j < 2; j++) {
            float* dst = As[buf];
            dst[(aq[j] * 4 + 0) * 132 + ar[j]] = areg[j].x;
            dst[(aq[j] * 4 + 1) * 132 + ar[j]] = areg[j].y;
            dst[(aq[j] * 4 + 2) * 132 + ar[j]] = areg[j].z;
            dst[(aq[j] * 4 + 3) * 132 + ar[j]] = areg[j].w;
        }
    };
    auto load_b = [&](int c, int buf) {                          // cp.async, 2x16B
        #pragma unroll
        for (int j = 0; j < 2; j++) {
            int idx = tid + 256 * j;
            int r = idx >> 5, cc = idx & 31;
            const float* gp = Bm + (size_t)(c * 16 + r) * ldb + colBase + cc * 4;
            CP_ASYNC16(bsm[buf] + (uint32_t)(r * 528 + cc * 16), gp);
        }
        CP_COMMIT();
    };

    constexpr int NCH = KTOT / 16;
    float4 areg[2];

    // prologue: chunk 0
    load_a(0, areg);
    load_b(0, 0);
    store_a(0, areg);
    CP_WAIT0();
    __syncthreads();

    for (int c = 0; c < NCH; c++) {
        const int buf = c & 1;
        if (c + 1 < NCH) {
            load_a(c + 1, areg);      // LDG latency hidden under compute below
            load_b(c + 1, buf ^ 1);
        }

        const float* Asb = As[buf];
        const float* Bsb = Bs[buf];
        #pragma unroll
        for (int kk = 0; kk < 16; kk++) {
            ulonglong2 a01 = *reinterpret_cast<const ulonglong2*>(&Asb[kk * 132 + ty * 8]);
            ulonglong2 a23 = *reinterpret_cast<const ulonglong2*>(&Asb[kk * 132 + ty * 8 + 4]);
            ull ap[4] = {a01.x, a01.y, a23.x, a23.y};
            float4 bv0 = *reinterpret_cast<const float4*>(&Bsb[kk * 132 + tx * 4]);
            float4 bv1 = *reinterpret_cast<const float4*>(&Bsb[kk * 132 + tx * 4 + 64]);
            ull bd[8] = {pack_dup(bv0.x), pack_dup(bv0.y), pack_dup(bv0.z), pack_dup(bv0.w),
                         pack_dup(bv1.x), pack_dup(bv1.y), pack_dup(bv1.z), pack_dup(bv1.w)};
            #pragma unroll
            for (int tp = 0; tp < 4; tp++)
                #pragma unroll
                for (int j = 0; j < 8; j++)
                    fma2(acc[tp][j], ap[tp], bd[j]);
        }

        if (c + 1 < NCH) {
            store_a(buf ^ 1, areg);
            CP_WAIT0();
        }
        __syncthreads();
    }
}

// ---------------- GEMM1: x = feat @ W1 + b1 ----------------
__global__ __launch_bounds__(256, 2)
void gemm1_kernel(const float* __restrict__ A, const float* __restrict__ W,
                  const float* __restrict__ bias) {
    extern __shared__ float sm[];
    const int tx = threadIdx.x & 15, ty = threadIdx.x >> 4;
    const int rowBase = blockIdx.y * 128, colBase = blockIdx.x * 128;

    ull acc[4][8];
    #pragma unroll
    for (int tp = 0; tp < 4; tp++)
        #pragma unroll
        for (int j = 0; j < 8; j++) acc[tp][j] = 0ull;

    mainloop_f32x2<H_>(A, H_, W, N1, rowBase, colBase, sm, acc);

    const int c0 = colBase + tx * 4;
    float4 bb0 = *reinterpret_cast<const float4*>(&bias[c0]);
    float4 bb1 = *reinterpret_cast<const float4*>(&bias[c0 + 64]);
    #pragma unroll
    for (int tp = 0; tp < 4; tp++) {
        float2 v[8];
        #pragma unroll
        for (int j = 0; j < 8; j++) v[j] = unpack2(acc[tp][j]);
        int m0 = rowBase + ty * 8 + tp * 2;
        *reinterpret_cast<float4*>(&g_x[(size_t)m0 * N1 + c0]) =
            make_float4(v[0].x + bb0.x, v[1].x + bb0.y, v[2].x + bb0.z, v[3].x + bb0.w);
        *reinterpret_cast<float4*>(&g_x[(size_t)m0 * N1 + c0 + 64]) =
            make_float4(v[4].x + bb1.x, v[5].x + bb1.y, v[6].x + bb1.z, v[7].x + bb1.w);
        *reinterpret_cast<float4*>(&g_x[(size_t)(m0 + 1) * N1 + c0]) =
            make_float4(v[0].y + bb0.x, v[1].y + bb0.y, v[2].y + bb0.z, v[3].y + bb0.w);
        *reinterpret_cast<float4*>(&g_x[(size_t)(m0 + 1) * N1 + c0 + 64]) =
            make_float4(v[4].y + bb1.x, v[5].y + bb1.y, v[6].y + bb1.z, v[7].y + bb1.w);
    }
}

// ---------------- RMS norm in place (R1 verbatim) ----------------
__global__ void rms_kernel(const float* __restrict__ norm_w) {
    const int seg = blockIdx.x;                 // b*8+t
    float* xp = g_x + (size_t)seg * F_;
    const int tid = threadIdx.x;                // 128

    float v[4];
    float ss = 0.f;
    #pragma unroll
    for (int i = 0; i < 4; i++) { v[i] = xp[tid + i * 128]; ss = fmaf(v[i], v[i], ss); }
    #pragma unroll
    for (int o = 16; o > 0; o >>= 1) ss += __shfl_xor_sync(0xffffffffu, ss, o);
    __shared__ float red[4];
    if ((tid & 31) == 0) red[tid >> 5] = ss;
    __syncthreads();
    float scale = rsqrtf((red[0] + red[1] + red[2] + red[3]) * (1.0f / F_) + RMS_EPS);
    #pragma unroll
    for (int i = 0; i < 4; i++)
        xp[tid + i * 128] = v[i] * scale * norm_w[tid + i * 128];
}

// ---------------- GEMM2 + loss epilogue (R7 math verbatim) ----------------
__global__ __launch_bounds__(256, 2)
void gemm2_loss_kernel(const float* __restrict__ W2, const float* __restrict__ b2,
                       const unsigned char* __restrict__ is_event,
                       const unsigned char* __restrict__ is_cen,
                       const float* __restrict__ ctr) {
    extern __shared__ float sm[];
    const int tid = threadIdx.x;
    const int tx = tid & 15, ty = tid >> 4;
    const int rowBase = blockIdx.y * 128, colBase = blockIdx.x * 128;
    const int bglob = blockIdx.y * 16 + ty;     // thread owns all 8 t of this b

    ull acc[4][8];
    #pragma unroll
    for (int tp = 0; tp < 4; tp++)
        #pragma unroll
        for (int j = 0; j < 8; j++) acc[tp][j] = 0ull;

    mainloop_f32x2<F_>(g_x, F_, W2, K_, rowBase, colBase, sm, acc);

    float lloss = 0.f;
    int lcnt = 0;
    #pragma unroll
    for (int j = 0; j < 8; j++) {
        const int k = colBase + tx * 4 + (j & 3) + ((j >= 4) ? 64 : 0);
        const float bb = b2[k];
        float lg[8];
        #pragma unroll
        for (int tp = 0; tp < 4; tp++) {
            float2 p2 = unpack2(acc[tp][j]);
            lg[tp * 2]     = p2.x + bb;
            lg[tp * 2 + 1] = p2.y + bb;
        }
        float mx = lg[0];
        #pragma unroll
        for (int t = 1; t < 8; t++) mx = fmaxf(mx, lg[t]);
        float e[8], s = 0.f;
        #pragma unroll
        for (int t = 0; t < 8; t++) { e[t] = __expf(lg[t] - mx); s += e[t]; }
        const float inv = 1.0f / s;

        const bool cen = is_cen[(size_t)bglob * K_ + k] != 0;
        float cdf = 0.f;
        #pragma unroll
        for (int t = 0; t < 8; t++) {
            const float p = e[t] * inv;
            if (is_event[((size_t)bglob * T_ + t) * K_ + k]) {
                float integrated = (t == 0) ? 1.0f : (1.0f - cdf);
                float p_s = fminf(fmaxf(p, EPSF), 1.0f - EPSF);
                float i_s = fminf(fmaxf(integrated, EPSF), 1.0f - EPSF);
                float sel;
                if (cen) {
                    float r = ctr[((size_t)bglob * T_ + t) * K_ + k];
                    i_s = fminf(fmaxf(i_s - r * p_s, EPSF), 1.0f - EPSF);
                    sel = i_s;
                } else {
                    sel = p_s;
                }
                lloss += __logf(sel);
                lcnt++;
            }
            cdf += p;
        }
    }

    #pragma unroll
    for (int o = 16; o > 0; o >>= 1) {
        lloss += __shfl_xor_sync(0xffffffffu, lloss, o);
        lcnt  += __shfl_xor_sync(0xffffffffu, lcnt, o);
    }
    __shared__ float rl[8];
    __shared__ int rc[8];
    if ((tid & 31) == 0) { rl[tid >> 5] = lloss; rc[tid >> 5] = lcnt; }
    __syncthreads();
    if (tid == 0) {
        float tl = 0.f; int tc = 0;
        #pragma unroll
        for (int w = 0; w < 8; w++) { tl += rl[w]; tc += rc[w]; }
        atomicAdd(&g_loss, (double)tl);
        atomicAdd(&g_count, (unsigned long long)tc);
    }
}

__global__ void finalize_kernel(float* __restrict__ out) {
    const double H_t = 2.0794415416798357;      // log(8)
    out[0] = (float)(-g_loss / ((double)g_count * H_t));
}

// ---------------- launch ----------------
extern "C" void kernel_launch(void* const* d_in, const int* in_sizes, int n_in,
                              void* d_out, int out_size) {
    const float* features = (const float*)d_in[0];
    const float* W1       = (const float*)d_in[1];
    const float* b1       = (const float*)d_in[2];
    const float* norm_w   = (const float*)d_in[3];
    const float* W2       = (const float*)d_in[4];
    const float* b2       = (const float*)d_in[5];
    const unsigned char* is_event    = (const unsigned char*)d_in[6];
    const unsigned char* is_censored = (const unsigned char*)d_in[7];
    const float* ctr      = (const float*)d_in[8];
    float* out = (float*)d_out;

    const int SMEM = 4 * TSZ * sizeof(float);   // 33792 B

    init_kernel<<<1, 1>>>();

    gemm1_kernel<<<dim3(N1 / 128, B_ / 128), 256, SMEM>>>(features, W1, b1);
    rms_kernel<<<B_ * T_, 128>>>(norm_w);

    gemm2_loss_kernel<<<dim3(K_ / 128, (B_ * T_) / 128), 256, SMEM>>>(W2, b2, is_event,
                                                                      is_censored, ctr);

    finalize_kernel<<<1, 1>>>(out);
}